// round 2
// baseline (speedup 1.0000x reference)
#include <cuda_runtime.h>
#include <math.h>

#define NSTEP 8192
#define NMOD  4096
#define DIM   1024
#define INVT  (1.0f / 0.07f)

typedef unsigned long long ull;

// ---------------- device scratch (static, no allocation) ----------------
__device__ float    g_inva[NSTEP];
__device__ float    g_invb[NMOD];
__device__ float    g_invc[NMOD];
__device__ unsigned g_negmax[NSTEP];   // ordered-uint encoded float max
__device__ float    g_perstep[NSTEP];
__device__ float    g_wsum[NSTEP];

// monotone float <-> uint encoding for atomicMax on signed floats
__device__ __forceinline__ unsigned fenc(float f) {
    unsigned u = __float_as_uint(f);
    return (u & 0x80000000u) ? ~u : (u | 0x80000000u);
}
__device__ __forceinline__ float fdec(unsigned u) {
    return (u & 0x80000000u) ? __uint_as_float(u & 0x7FFFFFFFu)
                             : __uint_as_float(~u);
}

// ---------------- packed f32x2 helpers ----------------
__device__ __forceinline__ ull pack_dup(float x) {
    ull r;
    asm("mov.b64 %0, {%1, %1};" : "=l"(r) : "f"(x));
    return r;
}
__device__ __forceinline__ void ffma2(ull& c, ull a, ull b) {
    asm("fma.rn.f32x2 %0, %1, %2, %0;" : "+l"(c) : "l"(a), "l"(b));
}
__device__ __forceinline__ float2 unpack2(ull v) {
    float2 r;
    asm("mov.b64 {%0, %1}, %2;" : "=f"(r.x), "=f"(r.y) : "l"(v));
    return r;
}

// ---------------- init (every launch: deterministic) ----------------
__global__ void init_kernel() {
    int i = blockIdx.x * 256 + threadIdx.x;
    if (i < NSTEP) g_negmax[i] = 0u;   // 0 < fenc(x) for all finite x
}

// ---------------- inverse norms ----------------
template <int WHICH>
__global__ void inv_norm_kernel(const float* __restrict__ X) {
    __shared__ float red[256];
    const int row = blockIdx.x;
    const int tid = threadIdx.x;
    const float4* p = reinterpret_cast<const float4*>(X + (size_t)row * DIM);
    float4 v = p[tid];                       // 1024 = 256 threads * 4 floats
    float s = v.x * v.x + v.y * v.y + v.z * v.z + v.w * v.w;
    red[tid] = s;
    __syncthreads();
    for (int off = 128; off > 0; off >>= 1) {
        if (tid < off) red[tid] += red[tid + off];
        __syncthreads();
    }
    if (tid == 0) {
        float inv = 1.0f / fmaxf(sqrtf(red[0]), 1e-8f);
        if (WHICH == 0)      g_inva[row] = inv;
        else if (WHICH == 1) g_invb[row] = inv;
        else                 g_invc[row] = inv;
    }
}

// ---------------- SGEMM (NT) with packed FFMA2: R = A * B^T ----------------
// MODE 0: write raw dots into Rout (the attention region of d_out)
// MODE 1: epilogue computes per-row max of R * invc[col] -> atomicMax
template <int MODE>
__global__ __launch_bounds__(256, 2)
void gemm_nt_kernel(const float* __restrict__ A, const float* __restrict__ B,
                    float* __restrict__ Rout) {
    __shared__ float As[16][128];
    __shared__ float Bs[16][128];
    const int tid = threadIdx.x;
    const int tx = tid & 15;         // column group
    const int ty = tid >> 4;         // row group
    const int rowBase = blockIdx.y * 128;
    const int colBase = blockIdx.x * 128;

    // 8 rows x 4 column-pairs of packed accumulators (= 8x8 fp32 outputs)
    ull acc[8][4];
#pragma unroll
    for (int i = 0; i < 8; i++)
#pragma unroll
        for (int j = 0; j < 4; j++) acc[i][j] = 0ull;

    const float* Ab = A + (size_t)rowBase * DIM;
    const float* Bb = B + (size_t)colBase * DIM;

    for (int k0 = 0; k0 < DIM; k0 += 16) {
        // cooperative loads: 128 rows x 16 k each for A and B (transposed store)
#pragma unroll
        for (int l = 0; l < 2; l++) {
            int id = tid + l * 256;
            int r  = id >> 2;
            int kq = (id & 3) << 2;
            float4 va = *reinterpret_cast<const float4*>(Ab + (size_t)r * DIM + k0 + kq);
            As[kq + 0][r] = va.x; As[kq + 1][r] = va.y;
            As[kq + 2][r] = va.z; As[kq + 3][r] = va.w;
            float4 vb = *reinterpret_cast<const float4*>(Bb + (size_t)r * DIM + k0 + kq);
            Bs[kq + 0][r] = vb.x; Bs[kq + 1][r] = vb.y;
            Bs[kq + 2][r] = vb.z; Bs[kq + 3][r] = vb.w;
        }
        __syncthreads();
#pragma unroll
        for (int k = 0; k < 16; k++) {
            float4 a0 = *reinterpret_cast<const float4*>(&As[k][ty * 8]);
            float4 a1 = *reinterpret_cast<const float4*>(&As[k][ty * 8 + 4]);
            ull aa[8];
            aa[0] = pack_dup(a0.x); aa[1] = pack_dup(a0.y);
            aa[2] = pack_dup(a0.z); aa[3] = pack_dup(a0.w);
            aa[4] = pack_dup(a1.x); aa[5] = pack_dup(a1.y);
            aa[6] = pack_dup(a1.z); aa[7] = pack_dup(a1.w);
            // b pairs: contiguous in shared, load directly as packed 64-bit
            ulonglong2 blo = *reinterpret_cast<const ulonglong2*>(&Bs[k][tx * 8]);
            ulonglong2 bhi = *reinterpret_cast<const ulonglong2*>(&Bs[k][tx * 8 + 4]);
            ull bb[4] = {blo.x, blo.y, bhi.x, bhi.y};
#pragma unroll
            for (int i = 0; i < 8; i++)
#pragma unroll
                for (int j = 0; j < 4; j++)
                    ffma2(acc[i][j], aa[i], bb[j]);
        }
        __syncthreads();
    }

    if (MODE == 0) {
        // write raw dot products (float2 stores: base d_out+2 is 8B aligned)
#pragma unroll
        for (int i = 0; i < 8; i++) {
            int row = rowBase + ty * 8 + i;
            float* dst = Rout + (size_t)row * NMOD + colBase + tx * 8;
#pragma unroll
            for (int j = 0; j < 4; j++)
                *reinterpret_cast<ull*>(dst + 2 * j) = acc[i][j];
        }
    } else {
        // per-row max of acc * invc[col]; reduce across the 16 column threads
        int col0 = colBase + tx * 8;
        float ic[8];
#pragma unroll
        for (int j = 0; j < 8; j++) ic[j] = g_invc[col0 + j];
#pragma unroll
        for (int i = 0; i < 8; i++) {
            float m = -3.402823466e38f;
#pragma unroll
            for (int j = 0; j < 4; j++) {
                float2 v2 = unpack2(acc[i][j]);
                m = fmaxf(m, v2.x * ic[2 * j]);
                m = fmaxf(m, v2.y * ic[2 * j + 1]);
            }
            As[tx][ty * 8 + i] = m;      // reuse As as [16][128] reduce buffer
        }
        __syncthreads();
        if (tid < 128) {
            float m = As[0][tid];
#pragma unroll
            for (int x = 1; x < 16; x++) m = fmaxf(m, As[x][tid]);
            atomicMax(&g_negmax[rowBase + tid], fenc(m));
        }
    }
}

// ---------------- per-row stats + softmax rewrite in place ----------------
__global__ void row_stats_kernel(float* __restrict__ attn,
                                 float* __restrict__ perstep_out) {
    __shared__ float red[256];
    __shared__ float bc[4];
    const int row = blockIdx.x;
    const int tid = threadIdx.x;
    float* Rrow = attn + (size_t)row * NMOD;

    float v[16], ib[16];
#pragma unroll
    for (int q = 0; q < 16; q++) {
        int j = tid + q * 256;
        v[q]  = Rrow[j];        // coalesced
        ib[q] = g_invb[j];
    }

    float mr = -3.402823466e38f, mrb = -3.402823466e38f;
#pragma unroll
    for (int q = 0; q < 16; q++) {
        mr  = fmaxf(mr, v[q]);
        mrb = fmaxf(mrb, v[q] * ib[q]);
    }

    // reduce max of raw dots (for softmax shift)
    red[tid] = mr; __syncthreads();
    for (int off = 128; off > 0; off >>= 1) {
        if (tid < off) red[tid] = fmaxf(red[tid], red[tid + off]);
        __syncthreads();
    }
    if (tid == 0) bc[0] = red[0];
    __syncthreads();

    // reduce max of scaled dots (per-step cosine max)
    red[tid] = mrb; __syncthreads();
    for (int off = 128; off > 0; off >>= 1) {
        if (tid < off) red[tid] = fmaxf(red[tid], red[tid + off]);
        __syncthreads();
    }
    if (tid == 0) bc[1] = red[0];
    __syncthreads();

    const float maxR = bc[0];
    float e[16];
    float dsum = 0.0f, ws = 0.0f;
#pragma unroll
    for (int q = 0; q < 16; q++) {
        float ev = __expf((v[q] - maxR) * INVT);
        e[q] = ev;
        dsum += ev;
        ws   += v[q] * ib[q] * ev;
    }

    red[tid] = dsum; __syncthreads();
    for (int off = 128; off > 0; off >>= 1) {
        if (tid < off) red[tid] += red[tid + off];
        __syncthreads();
    }
    if (tid == 0) bc[2] = red[0];
    __syncthreads();

    red[tid] = ws; __syncthreads();
    for (int off = 128; off > 0; off >>= 1) {
        if (tid < off) red[tid] += red[tid + off];
        __syncthreads();
    }
    if (tid == 0) bc[3] = red[0];
    __syncthreads();

    const float invd = 1.0f / bc[2];
#pragma unroll
    for (int q = 0; q < 16; q++)
        Rrow[tid + q * 256] = e[q] * invd;     // attention, in place

    if (tid == 0) {
        float inva = g_inva[row];
        float ps = bc[1] * inva;
        g_perstep[row]  = ps;
        perstep_out[row] = ps;
        g_wsum[row] = inva * bc[3] * invd;
    }
}

// ---------------- final scalar reductions ----------------
__global__ void finalize_kernel(float* __restrict__ out) {
    __shared__ float r0[1024], r1[1024], r2[1024], r3[1024];
    const int tid = threadIdx.x;
    float s = 0.0f, mn = 3.402823466e38f, ws = 0.0f, ng = 0.0f;
#pragma unroll
    for (int q = 0; q < 8; q++) {
        int i = tid + q * 1024;
        float ps = g_perstep[i];
        s += ps;
        mn = fminf(mn, ps);
        ws += g_wsum[i];
        ng += fdec(g_negmax[i]) * g_inva[i];
    }
    r0[tid] = s; r1[tid] = mn; r2[tid] = ws; r3[tid] = ng;
    __syncthreads();
    for (int off = 512; off > 0; off >>= 1) {
        if (tid < off) {
            r0[tid] += r0[tid + off];
            r1[tid] = fminf(r1[tid], r1[tid + off]);
            r2[tid] += r2[tid + off];
            r3[tid] += r3[tid + off];
        }
        __syncthreads();
    }
    if (tid == 0) {
        float alignment = r0[0] * (1.0f / NSTEP);
        float weighted  = r2[0] * (1.0f / NSTEP);
        float neg       = r3[0] * (1.0f / NSTEP);
        float contrast  = alignment - neg;
        float margin    = fmaxf(contrast - 0.2f, 0.0f);
        float overall   = 0.7f * weighted + 0.3f * contrast;
        out[0] = alignment;          // alignment
        out[1] = weighted;           // weighted_alignment
        float* t = out + 2 + (size_t)NSTEP * NMOD;   // after attention
        t[0] = contrast;             // contrastive_score
        t[1] = margin;               // margin_score
        t[2] = alignment;            // positive_alignment
        t[3] = neg;                  // negative_alignment
        // per_step written by row_stats_kernel at t[4 .. 4+NSTEP)
        t[4 + NSTEP] = r1[0];        // min_step_coherence
        t[5 + NSTEP] = overall;      // overall
    }
}

// ---------------- launch ----------------
extern "C" void kernel_launch(void* const* d_in, const int* in_sizes, int n_in,
                              void* d_out, int out_size) {
    (void)in_sizes; (void)n_in; (void)out_size;
    const float* A = (const float*)d_in[0];   // step_embeddings  [8192,1024]
    const float* B = (const float*)d_in[1];   // modal_embeddings [4096,1024]
    const float* C = (const float*)d_in[2];   // negatives        [4096,1024]
    float* out  = (float*)d_out;
    float* attn = out + 2;                                   // attention slot
    float* perstep = out + 2 + (size_t)NSTEP * NMOD + 4;     // per_step slot

    init_kernel<<<(NSTEP + 255) / 256, 256>>>();
    inv_norm_kernel<0><<<NSTEP, 256>>>(A);
    inv_norm_kernel<1><<<NMOD, 256>>>(B);
    inv_norm_kernel<2><<<NMOD, 256>>>(C);

    dim3 g(NMOD / 128, NSTEP / 128);
    gemm_nt_kernel<0><<<g, 256>>>(A, B, attn);      // raw dots -> attention slot
    gemm_nt_kernel<1><<<g, 256>>>(A, C, nullptr);   // fused neg-max epilogue

    row_stats_kernel<<<NSTEP, 256>>>(attn, perstep);
    finalize_kernel<<<1, 1024>>>(out);
}

// round 4
// speedup vs baseline: 1.2926x; 1.2926x over previous
#include <cuda_runtime.h>
#include <cstdint>
#include <math.h>

#define NSTEP 8192
#define NMOD  4096
#define DIM   1024
#define INVT  (1.0f / 0.07f)

#define KC 32
#define NCHUNK (DIM / KC)
#define STAGE_F 16384            // floats per stage (Ah,Al,Bh,Bl: 4 x 4096)
#define SMEM_BYTES (2 * STAGE_F * 4)

// ---------------- device scratch ----------------
__device__ float    g_inva[NSTEP];
__device__ float    g_invb[NMOD];
__device__ float    g_invc[NMOD];
__device__ unsigned g_negmax[NSTEP];
__device__ float    g_perstep[NSTEP];
__device__ float    g_wsum[NSTEP];

__device__ __forceinline__ unsigned fenc(float f) {
    unsigned u = __float_as_uint(f);
    return (u & 0x80000000u) ? ~u : (u | 0x80000000u);
}
__device__ __forceinline__ float fdec(unsigned u) {
    return (u & 0x80000000u) ? __uint_as_float(u & 0x7FFFFFFFu)
                             : __uint_as_float(~u);
}

__device__ __forceinline__ float tf32_rn(float x) {
    uint32_t r;
    asm("cvt.rna.tf32.f32 %0, %1;" : "=r"(r) : "f"(x));
    return __uint_as_float(r);
}

// m16n8k8 tf32 mma.sync (sm_80 PTX — compiles at plain sm_103 target)
__device__ __forceinline__ void mma8(float* c, const uint32_t* a, const uint32_t* b) {
    asm volatile(
        "mma.sync.aligned.m16n8k8.row.col.f32.tf32.tf32.f32 "
        "{%0,%1,%2,%3}, {%4,%5,%6,%7}, {%8,%9}, {%0,%1,%2,%3};"
        : "+f"(c[0]), "+f"(c[1]), "+f"(c[2]), "+f"(c[3])
        : "r"(a[0]), "r"(a[1]), "r"(a[2]), "r"(a[3]), "r"(b[0]), "r"(b[1]));
}

// ---------------- init ----------------
__global__ void init_kernel() {
    int i = blockIdx.x * 256 + threadIdx.x;
    if (i < NSTEP) g_negmax[i] = 0u;
}

// ---------------- inverse norms ----------------
template <int WHICH>
__global__ void inv_norm_kernel(const float* __restrict__ X) {
    __shared__ float red[256];
    const int row = blockIdx.x;
    const int tid = threadIdx.x;
    const float4* p = reinterpret_cast<const float4*>(X + (size_t)row * DIM);
    float4 v = p[tid];
    float s = v.x * v.x + v.y * v.y + v.z * v.z + v.w * v.w;
    red[tid] = s;
    __syncthreads();
    for (int off = 128; off > 0; off >>= 1) {
        if (tid < off) red[tid] += red[tid + off];
        __syncthreads();
    }
    if (tid == 0) {
        float inv = 1.0f / fmaxf(sqrtf(red[0]), 1e-8f);
        if (WHICH == 0)      g_inva[row] = inv;
        else if (WHICH == 1) g_invb[row] = inv;
        else                 g_invc[row] = inv;
    }
}

// ---------------- tf32 3-pass split GEMM via mma.sync ----------------
// Layout per stage (floats): Ah @0, Al @4096, Bh @8192, Bl @12288.
// Sub-layout: [k8(4)][row(128)][8], element k stored at pair slot (t^k8), half k>>2.
// MODE 0: write raw dots.  MODE 1: fused per-row neg-max epilogue.
template <int MODE>
__global__ __launch_bounds__(256, 1)
void gemm_mma(const float* __restrict__ A, const float* __restrict__ B,
              float* __restrict__ Rout) {
    extern __shared__ float smem[];
    const int tid  = threadIdx.x;
    const int lane = tid & 31;
    const int wid  = tid >> 5;
    const int g    = lane >> 2;       // group 0..7
    const int t    = lane & 3;        // thread-in-group
    const int wr   = wid >> 2;        // warp row 0..1  (64 rows each)
    const int wc   = wid & 3;         // warp col 0..3  (32 cols each)
    const int rowBase = blockIdx.y * 128;
    const int colBase = blockIdx.x * 128;

    const float* Ag = A + (size_t)rowBase * DIM;
    const float* Bg = B + (size_t)colBase * DIM;

    float acc[4][4][4];
#pragma unroll
    for (int i = 0; i < 4; i++)
#pragma unroll
        for (int j = 0; j < 4; j++)
#pragma unroll
            for (int q = 0; q < 4; q++) acc[i][j][q] = 0.0f;

    // per-thread gmem element mapping: f = tid + 256*i -> row=f>>3, kq=f&7
    int frow[4], fkq[4];
#pragma unroll
    for (int i = 0; i < 4; i++) {
        int f = tid + 256 * i;
        frow[i] = f >> 3;
        fkq[i]  = f & 7;
    }

    float4 pa[4], pb[4];
    // prologue: load chunk 0
#pragma unroll
    for (int i = 0; i < 4; i++) {
        pa[i] = *reinterpret_cast<const float4*>(Ag + (size_t)frow[i] * DIM + fkq[i] * 4);
        pb[i] = *reinterpret_cast<const float4*>(Bg + (size_t)frow[i] * DIM + fkq[i] * 4);
    }

    // split + STS helper (macro-ish via lambda)
    auto split_sts = [&](int buf) {
        float* S = smem + buf * STAGE_F;
#pragma unroll
        for (int i = 0; i < 4; i++) {
            int k8   = fkq[i] >> 1;
            int half = fkq[i] & 1;
            float* ba = S + k8 * 1024 + frow[i] * 8 + half;
            const float* va = reinterpret_cast<const float*>(&pa[i]);
            const float* vb = reinterpret_cast<const float*>(&pb[i]);
#pragma unroll
            for (int j = 0; j < 4; j++) {
                int pos = ((j ^ k8) << 1);
                float h = tf32_rn(va[j]);
                ba[pos]        = h;
                ba[pos + 4096] = tf32_rn(va[j] - h);
                float hb = tf32_rn(vb[j]);
                ba[pos + 8192]  = hb;
                ba[pos + 12288] = tf32_rn(vb[j] - hb);
            }
        }
    };

    split_sts(0);
    __syncthreads();

    for (int ch = 0; ch < NCHUNK; ch++) {
        const int buf = ch & 1;
        if (ch + 1 < NCHUNK) {
            const int k0 = (ch + 1) * KC;
#pragma unroll
            for (int i = 0; i < 4; i++) {
                pa[i] = *reinterpret_cast<const float4*>(Ag + (size_t)frow[i] * DIM + k0 + fkq[i] * 4);
                pb[i] = *reinterpret_cast<const float4*>(Bg + (size_t)frow[i] * DIM + k0 + fkq[i] * 4);
            }
        }

        const float* S = smem + buf * STAGE_F;
#pragma unroll
        for (int K = 0; K < 4; K++) {
            const float* SA = S + K * 1024;
            const float* SB = S + 8192 + K * 1024;
            const int tp = ((t ^ K) << 1);

            uint32_t ah[4][4], al[4][4];
#pragma unroll
            for (int mt = 0; mt < 4; mt++) {
                int r0 = (wr * 64 + mt * 16 + g) * 8;
                float2 h02 = *reinterpret_cast<const float2*>(SA + r0 + tp);
                float2 h13 = *reinterpret_cast<const float2*>(SA + r0 + 64 + tp);
                ah[mt][0] = __float_as_uint(h02.x); ah[mt][2] = __float_as_uint(h02.y);
                ah[mt][1] = __float_as_uint(h13.x); ah[mt][3] = __float_as_uint(h13.y);
                float2 l02 = *reinterpret_cast<const float2*>(SA + 4096 + r0 + tp);
                float2 l13 = *reinterpret_cast<const float2*>(SA + 4096 + r0 + 64 + tp);
                al[mt][0] = __float_as_uint(l02.x); al[mt][2] = __float_as_uint(l02.y);
                al[mt][1] = __float_as_uint(l13.x); al[mt][3] = __float_as_uint(l13.y);
            }
            uint32_t bh[4][2], bl[4][2];
#pragma unroll
            for (int nt = 0; nt < 4; nt++) {
                int c0 = (wc * 32 + nt * 8 + g) * 8;
                float2 h2 = *reinterpret_cast<const float2*>(SB + c0 + tp);
                bh[nt][0] = __float_as_uint(h2.x); bh[nt][1] = __float_as_uint(h2.y);
                float2 l2 = *reinterpret_cast<const float2*>(SB + 4096 + c0 + tp);
                bl[nt][0] = __float_as_uint(l2.x); bl[nt][1] = __float_as_uint(l2.y);
            }
            // three passes: ah*bh, ah*bl, al*bh
#pragma unroll
            for (int mt = 0; mt < 4; mt++)
#pragma unroll
                for (int nt = 0; nt < 4; nt++) mma8(acc[mt][nt], ah[mt], bh[nt]);
#pragma unroll
            for (int mt = 0; mt < 4; mt++)
#pragma unroll
                for (int nt = 0; nt < 4; nt++) mma8(acc[mt][nt], ah[mt], bl[nt]);
#pragma unroll
            for (int mt = 0; mt < 4; mt++)
#pragma unroll
                for (int nt = 0; nt < 4; nt++) mma8(acc[mt][nt], al[mt], bh[nt]);
        }

        if (ch + 1 < NCHUNK) split_sts(buf ^ 1);
        __syncthreads();
    }

    // ---------------- epilogue ----------------
    if (MODE == 0) {
#pragma unroll
        for (int mt = 0; mt < 4; mt++) {
            int r = rowBase + wr * 64 + mt * 16 + g;
#pragma unroll
            for (int nt = 0; nt < 4; nt++) {
                int c = colBase + wc * 32 + nt * 8 + 2 * t;
                *reinterpret_cast<float2*>(Rout + (size_t)r * NMOD + c) =
                    make_float2(acc[mt][nt][0], acc[mt][nt][1]);
                *reinterpret_cast<float2*>(Rout + (size_t)(r + 8) * NMOD + c) =
                    make_float2(acc[mt][nt][2], acc[mt][nt][3]);
            }
        }
    } else {
        float mx0[4], mx1[4];
#pragma unroll
        for (int mt = 0; mt < 4; mt++) { mx0[mt] = -3.402823466e38f; mx1[mt] = -3.402823466e38f; }
#pragma unroll
        for (int nt = 0; nt < 4; nt++) {
            int c = colBase + wc * 32 + nt * 8 + 2 * t;
            float ic0 = g_invc[c], ic1 = g_invc[c + 1];
#pragma unroll
            for (int mt = 0; mt < 4; mt++) {
                mx0[mt] = fmaxf(mx0[mt], fmaxf(acc[mt][nt][0] * ic0, acc[mt][nt][1] * ic1));
                mx1[mt] = fmaxf(mx1[mt], fmaxf(acc[mt][nt][2] * ic0, acc[mt][nt][3] * ic1));
            }
        }
#pragma unroll
        for (int mt = 0; mt < 4; mt++) {
            mx0[mt] = fmaxf(mx0[mt], __shfl_xor_sync(0xFFFFFFFF, mx0[mt], 1));
            mx0[mt] = fmaxf(mx0[mt], __shfl_xor_sync(0xFFFFFFFF, mx0[mt], 2));
            mx1[mt] = fmaxf(mx1[mt], __shfl_xor_sync(0xFFFFFFFF, mx1[mt], 1));
            mx1[mt] = fmaxf(mx1[mt], __shfl_xor_sync(0xFFFFFFFF, mx1[mt], 2));
        }
        if (t == 0) {
#pragma unroll
            for (int mt = 0; mt < 4; mt++) {
                int r = rowBase + wr * 64 + mt * 16 + g;
                atomicMax(&g_negmax[r], fenc(mx0[mt]));
                atomicMax(&g_negmax[r + 8], fenc(mx1[mt]));
            }
        }
    }
}

// ---------------- per-row stats + softmax rewrite in place ----------------
__global__ void row_stats_kernel(float* __restrict__ attn,
                                 float* __restrict__ perstep_out) {
    __shared__ float red[256];
    __shared__ float bc[4];
    const int row = blockIdx.x;
    const int tid = threadIdx.x;
    float* Rrow = attn + (size_t)row * NMOD;

    float v[16], ib[16];
#pragma unroll
    for (int q = 0; q < 16; q++) {
        int j = tid + q * 256;
        v[q]  = Rrow[j];
        ib[q] = g_invb[j];
    }

    float mr = -3.402823466e38f, mrb = -3.402823466e38f;
#pragma unroll
    for (int q = 0; q < 16; q++) {
        mr  = fmaxf(mr, v[q]);
        mrb = fmaxf(mrb, v[q] * ib[q]);
    }

    red[tid] = mr; __syncthreads();
    for (int off = 128; off > 0; off >>= 1) {
        if (tid < off) red[tid] = fmaxf(red[tid], red[tid + off]);
        __syncthreads();
    }
    if (tid == 0) bc[0] = red[0];
    __syncthreads();

    red[tid] = mrb; __syncthreads();
    for (int off = 128; off > 0; off >>= 1) {
        if (tid < off) red[tid] = fmaxf(red[tid], red[tid + off]);
        __syncthreads();
    }
    if (tid == 0) bc[1] = red[0];
    __syncthreads();

    const float maxR = bc[0];
    float e[16];
    float dsum = 0.0f, ws = 0.0f;
#pragma unroll
    for (int q = 0; q < 16; q++) {
        float ev = __expf((v[q] - maxR) * INVT);
        e[q] = ev;
        dsum += ev;
        ws   += v[q] * ib[q] * ev;
    }

    red[tid] = dsum; __syncthreads();
    for (int off = 128; off > 0; off >>= 1) {
        if (tid < off) red[tid] += red[tid + off];
        __syncthreads();
    }
    if (tid == 0) bc[2] = red[0];
    __syncthreads();

    red[tid] = ws; __syncthreads();
    for (int off = 128; off > 0; off >>= 1) {
        if (tid < off) red[tid] += red[tid + off];
        __syncthreads();
    }
    if (tid == 0) bc[3] = red[0];
    __syncthreads();

    const float invd = 1.0f / bc[2];
#pragma unroll
    for (int q = 0; q < 16; q++)
        Rrow[tid + q * 256] = e[q] * invd;

    if (tid == 0) {
        float inva = g_inva[row];
        float ps = bc[1] * inva;
        g_perstep[row]  = ps;
        perstep_out[row] = ps;
        g_wsum[row] = inva * bc[3] * invd;
    }
}

// ---------------- final scalar reductions ----------------
__global__ void finalize_kernel(float* __restrict__ out) {
    __shared__ float r0[1024], r1[1024], r2[1024], r3[1024];
    const int tid = threadIdx.x;
    float s = 0.0f, mn = 3.402823466e38f, ws = 0.0f, ng = 0.0f;
#pragma unroll
    for (int q = 0; q < 8; q++) {
        int i = tid + q * 1024;
        float ps = g_perstep[i];
        s += ps;
        mn = fminf(mn, ps);
        ws += g_wsum[i];
        ng += fdec(g_negmax[i]) * g_inva[i];
    }
    r0[tid] = s; r1[tid] = mn; r2[tid] = ws; r3[tid] = ng;
    __syncthreads();
    for (int off = 512; off > 0; off >>= 1) {
        if (tid < off) {
            r0[tid] += r0[tid + off];
            r1[tid] = fminf(r1[tid], r1[tid + off]);
            r2[tid] += r2[tid + off];
            r3[tid] += r3[tid + off];
        }
        __syncthreads();
    }
    if (tid == 0) {
        float alignment = r0[0] * (1.0f / NSTEP);
        float weighted  = r2[0] * (1.0f / NSTEP);
        float neg       = r3[0] * (1.0f / NSTEP);
        float contrast  = alignment - neg;
        float margin    = fmaxf(contrast - 0.2f, 0.0f);
        float overall   = 0.7f * weighted + 0.3f * contrast;
        out[0] = alignment;
        out[1] = weighted;
        float* tl = out + 2 + (size_t)NSTEP * NMOD;
        tl[0] = contrast;
        tl[1] = margin;
        tl[2] = alignment;
        tl[3] = neg;
        tl[4 + NSTEP] = r1[0];
        tl[5 + NSTEP] = overall;
    }
}

// ---------------- launch ----------------
extern "C" void kernel_launch(void* const* d_in, const int* in_sizes, int n_in,
                              void* d_out, int out_size) {
    (void)in_sizes; (void)n_in; (void)out_size;
    const float* A = (const float*)d_in[0];
    const float* B = (const float*)d_in[1];
    const float* C = (const float*)d_in[2];
    float* out  = (float*)d_out;
    float* attn = out + 2;
    float* perstep = out + 2 + (size_t)NSTEP * NMOD + 4;

    cudaFuncSetAttribute(gemm_mma<0>, cudaFuncAttributeMaxDynamicSharedMemorySize, SMEM_BYTES);
    cudaFuncSetAttribute(gemm_mma<1>, cudaFuncAttributeMaxDynamicSharedMemorySize, SMEM_BYTES);

    init_kernel<<<(NSTEP + 255) / 256, 256>>>();
    inv_norm_kernel<0><<<NSTEP, 256>>>(A);
    inv_norm_kernel<1><<<NMOD, 256>>>(B);
    inv_norm_kernel<2><<<NMOD, 256>>>(C);

    dim3 g(NMOD / 128, NSTEP / 128);
    gemm_mma<0><<<g, 256, SMEM_BYTES>>>(A, B, attn);
    gemm_mma<1><<<g, 256, SMEM_BYTES>>>(A, C, nullptr);

    row_stats_kernel<<<NSTEP, 256>>>(attn, perstep);
    finalize_kernel<<<1, 1024>>>(out);
}

// round 6
// speedup vs baseline: 1.5790x; 1.2216x over previous
#include <cuda_runtime.h>
#include <cstdint>
#include <math.h>

#define NSTEP 8192
#define NMOD  4096
#define DIM   1024
#define INVT  (1.0f / 0.07f)

#define KC 32
#define NCHUNK (DIM / KC)
#define STAGE_F 16384                 // floats per stage: Ah,Al,Bh,Bl 4x4096
#define SMEM_BYTES (3 * STAGE_F * 4)  // 192KB, triple buffered

// ---------------- device scratch (static, allowed) ----------------
// fragment-major split layout, per (tile,chunk) block of 8192 floats:
//   A block: Ah[m16(8)][k8(4)][lane(32)][q(4)] @0, Al @4096
//   B block: Bh[n8(16)][lane(32)][k8(4)][r(2)] @0, Bl @4096
__device__ float g_As[(size_t)64 * NCHUNK * 8192];
__device__ float g_Bs[(size_t)32 * NCHUNK * 8192];
__device__ float g_Cs[(size_t)32 * NCHUNK * 8192];

__device__ float    g_inva[NSTEP];
__device__ float    g_invb[NMOD];
__device__ float    g_invc[NMOD];
__device__ unsigned g_negmax[NSTEP];
__device__ float    g_perstep[NSTEP];
__device__ float    g_wsum[NSTEP];

__device__ __forceinline__ unsigned fenc(float f) {
    unsigned u = __float_as_uint(f);
    return (u & 0x80000000u) ? ~u : (u | 0x80000000u);
}
__device__ __forceinline__ float fdec(unsigned u) {
    return (u & 0x80000000u) ? __uint_as_float(u & 0x7FFFFFFFu)
                             : __uint_as_float(~u);
}
__device__ __forceinline__ float tf32_rn(float x) {
    uint32_t r;
    asm("cvt.rna.tf32.f32 %0, %1;" : "=r"(r) : "f"(x));
    return __uint_as_float(r);
}
__device__ __forceinline__ uint32_t smem_u32(const void* p) {
    uint32_t a;
    asm("{ .reg .u64 t; cvta.to.shared.u64 t, %1; cvt.u32.u64 %0, t; }"
        : "=r"(a) : "l"(p));
    return a;
}
__device__ __forceinline__ void cp16(uint32_t dst, const void* src) {
    asm volatile("cp.async.cg.shared.global [%0], [%1], 16;"
                 :: "r"(dst), "l"(src) : "memory");
}
__device__ __forceinline__ void mma8(float* c, const uint32_t* a, const uint32_t* b) {
    asm volatile(
        "mma.sync.aligned.m16n8k8.row.col.f32.tf32.tf32.f32 "
        "{%0,%1,%2,%3}, {%4,%5,%6,%7}, {%8,%9}, {%0,%1,%2,%3};"
        : "+f"(c[0]), "+f"(c[1]), "+f"(c[2]), "+f"(c[3])
        : "r"(a[0]), "r"(a[1]), "r"(a[2]), "r"(a[3]), "r"(b[0]), "r"(b[1]));
}

// ---------------- init ----------------
__global__ void init_kernel() {
    int i = blockIdx.x * 256 + threadIdx.x;
    if (i < NSTEP) g_negmax[i] = 0u;
}

// ---------------- inverse norms ----------------
template <int WHICH>
__global__ void inv_norm_kernel(const float* __restrict__ X) {
    __shared__ float red[256];
    const int row = blockIdx.x;
    const int tid = threadIdx.x;
    const float4* p = reinterpret_cast<const float4*>(X + (size_t)row * DIM);
    float4 v = p[tid];
    float s = v.x * v.x + v.y * v.y + v.z * v.z + v.w * v.w;
    red[tid] = s;
    __syncthreads();
    for (int off = 128; off > 0; off >>= 1) {
        if (tid < off) red[tid] += red[tid + off];
        __syncthreads();
    }
    if (tid == 0) {
        float inv = 1.0f / fmaxf(sqrtf(red[0]), 1e-8f);
        if (WHICH == 0)      g_inva[row] = inv;
        else if (WHICH == 1) g_invb[row] = inv;
        else                 g_invc[row] = inv;
    }
}

// ---------------- pre-split A (row operand) into fragment-major hi/lo ----------------
__global__ void split_a_kernel(const float* __restrict__ src, float* __restrict__ dst) {
    const int ch = blockIdx.x, rb = blockIdx.y;
    const int tid = threadIdx.x;
    float* base = dst + ((size_t)rb * NCHUNK + ch) * 8192;
    const float* sp = src + (size_t)rb * 128 * DIM + ch * KC;
#pragma unroll
    for (int i = 0; i < 4; i++) {
        int s = tid + i * 256;               // slot: [m16(8)][k8(4)][lane(32)]
        int m16 = s >> 7, k8 = (s >> 5) & 3, l = s & 31;
        int gg = l >> 2, tt = l & 3;
        float h[4], lo[4];
#pragma unroll
        for (int q = 0; q < 4; q++) {
            int row = m16 * 16 + gg + (q & 1) * 8;
            int k   = k8 * 8 + tt + (q >> 1) * 4;
            float v = sp[(size_t)row * DIM + k];
            h[q]  = tf32_rn(v);
            lo[q] = tf32_rn(v - h[q]);
        }
        *reinterpret_cast<float4*>(base + s * 4) = make_float4(h[0], h[1], h[2], h[3]);
        *reinterpret_cast<float4*>(base + 4096 + s * 4) = make_float4(lo[0], lo[1], lo[2], lo[3]);
    }
}

// ---------------- pre-split B/C (col operand) ----------------
__global__ void split_b_kernel(const float* __restrict__ src, float* __restrict__ dst) {
    const int ch = blockIdx.x, cb = blockIdx.y;
    const int tid = threadIdx.x;
    float* base = dst + ((size_t)cb * NCHUNK + ch) * 8192;
    const float* sp = src + (size_t)cb * 128 * DIM + ch * KC;
#pragma unroll
    for (int i = 0; i < 2; i++) {
        int s = tid + i * 256;               // slot: [n8(16)][lane(32)]
        int n8 = s >> 5, l = s & 31;
        int gg = l >> 2, tt = l & 3;
        const float* rp = sp + (size_t)(n8 * 8 + gg) * DIM + tt;
        float h[8], lo[8];
#pragma unroll
        for (int k8 = 0; k8 < 4; k8++)
#pragma unroll
            for (int r = 0; r < 2; r++) {
                float v = rp[k8 * 8 + r * 4];
                int o = k8 * 2 + r;
                h[o]  = tf32_rn(v);
                lo[o] = tf32_rn(v - h[o]);
            }
        float4* dh = reinterpret_cast<float4*>(base + s * 8);
        dh[0] = make_float4(h[0], h[1], h[2], h[3]);
        dh[1] = make_float4(h[4], h[5], h[6], h[7]);
        float4* dl = reinterpret_cast<float4*>(base + 4096 + s * 8);
        dl[0] = make_float4(lo[0], lo[1], lo[2], lo[3]);
        dl[1] = make_float4(lo[4], lo[5], lo[6], lo[7]);
    }
}

// ---------------- GEMM from pre-split scratch, cp.async 3-stage ----------------
// Always full 3-pass (fp32-accurate). MODE selects epilogue only:
// MODE 0: write raw dots.  MODE 1: fused per-row neg-max (no matrix store).
template <int MODE>
__global__ __launch_bounds__(256, 1)
void gemm_mma(const float* __restrict__ Ascr, const float* __restrict__ Bscr,
              float* __restrict__ Rout) {
    extern __shared__ float smem[];
    const int tid = threadIdx.x, lane = tid & 31, wid = tid >> 5;
    const int g = lane >> 2, t = lane & 3;
    const int wr = wid >> 2, wc = wid & 3;
    const int rowBase = blockIdx.y * 128, colBase = blockIdx.x * 128;
    const uint32_t sb0 = smem_u32(smem);
    const float* Ablk = Ascr + (size_t)blockIdx.y * NCHUNK * 8192;
    const float* Bblk = Bscr + (size_t)blockIdx.x * NCHUNK * 8192;

    float acc[4][4][4];
#pragma unroll
    for (int i = 0; i < 4; i++)
#pragma unroll
        for (int j = 0; j < 4; j++)
#pragma unroll
            for (int q = 0; q < 4; q++) acc[i][j][q] = 0.0f;

    auto issue = [&](int ch, int stg) {
        uint32_t sb = sb0 + stg * (STAGE_F * 4);
        const float* as = Ablk + (size_t)ch * 8192;
        const float* bs = Bblk + (size_t)ch * 8192;
#pragma unroll
        for (int q = 0; q < 8; q++) {
            int o = (tid + q * 256) * 4;        // float offset
            cp16(sb + o * 4, as + o);
            cp16(sb + 32768 + o * 4, bs + o);
        }
        asm volatile("cp.async.commit_group;" ::: "memory");
    };

    issue(0, 0);
    issue(1, 1);

    for (int ch = 0; ch < NCHUNK; ch++) {
        if (ch == NCHUNK - 1)
            asm volatile("cp.async.wait_group 0;" ::: "memory");
        else
            asm volatile("cp.async.wait_group 1;" ::: "memory");
        __syncthreads();
        if (ch + 2 < NCHUNK) issue(ch + 2, (ch + 2) % 3);

        const float* S  = smem + (ch % 3) * STAGE_F;
        const float* SB = S + 8192;

#pragma unroll
        for (int Kp = 0; Kp < 2; Kp++) {
            float4 bfh[4], bfl[4];
#pragma unroll
            for (int nt = 0; nt < 4; nt++) {
                const float* bp = SB + ((wc * 4 + nt) * 32 + lane) * 8 + Kp * 4;
                bfh[nt] = *reinterpret_cast<const float4*>(bp);
                bfl[nt] = *reinterpret_cast<const float4*>(bp + 4096);
            }
#pragma unroll
            for (int K2 = 0; K2 < 2; K2++) {
                const int K = Kp * 2 + K2;
                uint32_t ah[4][4], al[4][4];
#pragma unroll
                for (int mt = 0; mt < 4; mt++) {
                    const float* ap = S + (((wr * 4 + mt) * 4 + K) * 32 + lane) * 4;
                    float4 v = *reinterpret_cast<const float4*>(ap);
                    ah[mt][0] = __float_as_uint(v.x); ah[mt][1] = __float_as_uint(v.y);
                    ah[mt][2] = __float_as_uint(v.z); ah[mt][3] = __float_as_uint(v.w);
                    float4 w = *reinterpret_cast<const float4*>(ap + 4096);
                    al[mt][0] = __float_as_uint(w.x); al[mt][1] = __float_as_uint(w.y);
                    al[mt][2] = __float_as_uint(w.z); al[mt][3] = __float_as_uint(w.w);
                }
                uint32_t bh[4][2], bl[4][2];
#pragma unroll
                for (int nt = 0; nt < 4; nt++) {
                    bh[nt][0] = __float_as_uint(K2 ? bfh[nt].z : bfh[nt].x);
                    bh[nt][1] = __float_as_uint(K2 ? bfh[nt].w : bfh[nt].y);
                    bl[nt][0] = __float_as_uint(K2 ? bfl[nt].z : bfl[nt].x);
                    bl[nt][1] = __float_as_uint(K2 ? bfl[nt].w : bfl[nt].y);
                }
#pragma unroll
                for (int mt = 0; mt < 4; mt++)
#pragma unroll
                    for (int nt = 0; nt < 4; nt++) mma8(acc[mt][nt], ah[mt], bh[nt]);
#pragma unroll
                for (int mt = 0; mt < 4; mt++)
#pragma unroll
                    for (int nt = 0; nt < 4; nt++) mma8(acc[mt][nt], ah[mt], bl[nt]);
#pragma unroll
                for (int mt = 0; mt < 4; mt++)
#pragma unroll
                    for (int nt = 0; nt < 4; nt++) mma8(acc[mt][nt], al[mt], bh[nt]);
            }
        }
    }

    // ---------------- epilogue ----------------
    if (MODE == 0) {
#pragma unroll
        for (int mt = 0; mt < 4; mt++) {
            int r = rowBase + wr * 64 + mt * 16 + g;
#pragma unroll
            for (int nt = 0; nt < 4; nt++) {
                int c = colBase + wc * 32 + nt * 8 + 2 * t;
                *reinterpret_cast<float2*>(Rout + (size_t)r * NMOD + c) =
                    make_float2(acc[mt][nt][0], acc[mt][nt][1]);
                *reinterpret_cast<float2*>(Rout + (size_t)(r + 8) * NMOD + c) =
                    make_float2(acc[mt][nt][2], acc[mt][nt][3]);
            }
        }
    } else {
        float mx0[4], mx1[4];
#pragma unroll
        for (int mt = 0; mt < 4; mt++) { mx0[mt] = -3.402823466e38f; mx1[mt] = -3.402823466e38f; }
#pragma unroll
        for (int nt = 0; nt < 4; nt++) {
            int c = colBase + wc * 32 + nt * 8 + 2 * t;
            float ic0 = g_invc[c], ic1 = g_invc[c + 1];
#pragma unroll
            for (int mt = 0; mt < 4; mt++) {
                mx0[mt] = fmaxf(mx0[mt], fmaxf(acc[mt][nt][0] * ic0, acc[mt][nt][1] * ic1));
                mx1[mt] = fmaxf(mx1[mt], fmaxf(acc[mt][nt][2] * ic0, acc[mt][nt][3] * ic1));
            }
        }
#pragma unroll
        for (int mt = 0; mt < 4; mt++) {
            mx0[mt] = fmaxf(mx0[mt], __shfl_xor_sync(0xFFFFFFFF, mx0[mt], 1));
            mx0[mt] = fmaxf(mx0[mt], __shfl_xor_sync(0xFFFFFFFF, mx0[mt], 2));
            mx1[mt] = fmaxf(mx1[mt], __shfl_xor_sync(0xFFFFFFFF, mx1[mt], 1));
            mx1[mt] = fmaxf(mx1[mt], __shfl_xor_sync(0xFFFFFFFF, mx1[mt], 2));
        }
        if (t == 0) {
#pragma unroll
            for (int mt = 0; mt < 4; mt++) {
                int r = rowBase + wr * 64 + mt * 16 + g;
                atomicMax(&g_negmax[r], fenc(mx0[mt]));
                atomicMax(&g_negmax[r + 8], fenc(mx1[mt]));
            }
        }
    }
}

// ---------------- per-row stats + softmax rewrite in place ----------------
__global__ void row_stats_kernel(float* __restrict__ attn,
                                 float* __restrict__ perstep_out) {
    __shared__ float red[256];
    __shared__ float bc[4];
    const int row = blockIdx.x;
    const int tid = threadIdx.x;
    float* Rrow = attn + (size_t)row * NMOD;

    float v[16], ib[16];
#pragma unroll
    for (int q = 0; q < 16; q++) {
        int j = tid + q * 256;
        v[q]  = Rrow[j];
        ib[q] = g_invb[j];
    }

    float mr = -3.402823466e38f, mrb = -3.402823466e38f;
#pragma unroll
    for (int q = 0; q < 16; q++) {
        mr  = fmaxf(mr, v[q]);
        mrb = fmaxf(mrb, v[q] * ib[q]);
    }

    red[tid] = mr; __syncthreads();
    for (int off = 128; off > 0; off >>= 1) {
        if (tid < off) red[tid] = fmaxf(red[tid], red[tid + off]);
        __syncthreads();
    }
    if (tid == 0) bc[0] = red[0];
    __syncthreads();

    red[tid] = mrb; __syncthreads();
    for (int off = 128; off > 0; off >>= 1) {
        if (tid < off) red[tid] = fmaxf(red[tid], red[tid + off]);
        __syncthreads();
    }
    if (tid == 0) bc[1] = red[0];
    __syncthreads();

    const float maxR = bc[0];
    float e[16];
    float dsum = 0.0f, ws = 0.0f;
#pragma unroll
    for (int q = 0; q < 16; q++) {
        float ev = __expf((v[q] - maxR) * INVT);
        e[q] = ev;
        dsum += ev;
        ws   += v[q] * ib[q] * ev;
    }

    red[tid] = dsum; __syncthreads();
    for (int off = 128; off > 0; off >>= 1) {
        if (tid < off) red[tid] += red[tid + off];
        __syncthreads();
    }
    if (tid == 0) bc[2] = red[0];
    __syncthreads();

    red[tid] = ws; __syncthreads();
    for (int off = 128; off > 0; off >>= 1) {
        if (tid < off) red[tid] += red[tid + off];
        __syncthreads();
    }
    if (tid == 0) bc[3] = red[0];
    __syncthreads();

    const float invd = 1.0f / bc[2];
#pragma unroll
    for (int q = 0; q < 16; q++)
        Rrow[tid + q * 256] = e[q] * invd;

    if (tid == 0) {
        float inva = g_inva[row];
        float ps = bc[1] * inva;
        g_perstep[row]  = ps;
        perstep_out[row] = ps;
        g_wsum[row] = inva * bc[3] * invd;
    }
}

// ---------------- final scalar reductions ----------------
__global__ void finalize_kernel(float* __restrict__ out) {
    __shared__ float r0[1024], r1[1024], r2[1024], r3[1024];
    const int tid = threadIdx.x;
    float s = 0.0f, mn = 3.402823466e38f, ws = 0.0f, ng = 0.0f;
#pragma unroll
    for (int q = 0; q < 8; q++) {
        int i = tid + q * 1024;
        float ps = g_perstep[i];
        s += ps;
        mn = fminf(mn, ps);
        ws += g_wsum[i];
        ng += fdec(g_negmax[i]) * g_inva[i];
    }
    r0[tid] = s; r1[tid] = mn; r2[tid] = ws; r3[tid] = ng;
    __syncthreads();
    for (int off = 512; off > 0; off >>= 1) {
        if (tid < off) {
            r0[tid] += r0[tid + off];
            r1[tid] = fminf(r1[tid], r1[tid + off]);
            r2[tid] += r2[tid + off];
            r3[tid] += r3[tid + off];
        }
        __syncthreads();
    }
    if (tid == 0) {
        float alignment = r0[0] * (1.0f / NSTEP);
        float weighted  = r2[0] * (1.0f / NSTEP);
        float neg       = r3[0] * (1.0f / NSTEP);
        float contrast  = alignment - neg;
        float margin    = fmaxf(contrast - 0.2f, 0.0f);
        float overall   = 0.7f * weighted + 0.3f * contrast;
        out[0] = alignment;
        out[1] = weighted;
        float* tl = out + 2 + (size_t)NSTEP * NMOD;
        tl[0] = contrast;
        tl[1] = margin;
        tl[2] = alignment;
        tl[3] = neg;
        tl[4 + NSTEP] = r1[0];
        tl[5 + NSTEP] = overall;
    }
}

// ---------------- launch ----------------
extern "C" void kernel_launch(void* const* d_in, const int* in_sizes, int n_in,
                              void* d_out, int out_size) {
    (void)in_sizes; (void)n_in; (void)out_size;
    const float* A = (const float*)d_in[0];
    const float* B = (const float*)d_in[1];
    const float* C = (const float*)d_in[2];
    float* out  = (float*)d_out;
    float* attn = out + 2;
    float* perstep = out + 2 + (size_t)NSTEP * NMOD + 4;

    float* As_p; cudaGetSymbolAddress((void**)&As_p, g_As);
    float* Bs_p; cudaGetSymbolAddress((void**)&Bs_p, g_Bs);
    float* Cs_p; cudaGetSymbolAddress((void**)&Cs_p, g_Cs);

    cudaFuncSetAttribute(gemm_mma<0>, cudaFuncAttributeMaxDynamicSharedMemorySize, SMEM_BYTES);
    cudaFuncSetAttribute(gemm_mma<1>, cudaFuncAttributeMaxDynamicSharedMemorySize, SMEM_BYTES);

    init_kernel<<<(NSTEP + 255) / 256, 256>>>();
    inv_norm_kernel<0><<<NSTEP, 256>>>(A);
    inv_norm_kernel<1><<<NMOD, 256>>>(B);
    inv_norm_kernel<2><<<NMOD, 256>>>(C);

    split_a_kernel<<<dim3(NCHUNK, 64), 256>>>(A, As_p);
    split_b_kernel<<<dim3(NCHUNK, 32), 256>>>(B, Bs_p);
    split_b_kernel<<<dim3(NCHUNK, 32), 256>>>(C, Cs_p);

    dim3 g(NMOD / 128, NSTEP / 128);
    gemm_mma<0><<<g, 256, SMEM_BYTES>>>(As_p, Bs_p, attn);
    gemm_mma<1><<<g, 256, SMEM_BYTES>>>(As_p, Cs_p, nullptr);

    row_stats_kernel<<<NSTEP, 256>>>(attn, perstep);
    finalize_kernel<<<1, 1024>>>(out);
}

// round 7
// speedup vs baseline: 2.7621x; 1.7493x over previous
#include <cuda_runtime.h>
#include <cuda_fp16.h>
#include <cstdint>
#include <math.h>

#define NSTEP 8192
#define NMOD  4096
#define DIM   1024
#define INVT  (1.0f / 0.07f)

#define KC 32
#define NCHUNK (DIM / KC)
#define STAGE_H 16384                  // halves per stage: Ah,Al,Bh,Bl 4x4096
#define STAGE_BYTES (STAGE_H * 2)      // 32KB
#define NSTAGE 4
#define SMEM_BYTES (NSTAGE * STAGE_BYTES)  // 128KB

// ---------------- device scratch (static, allowed) ----------------
// per (tile,chunk) block of 8192 halves:
//   A block: Ah[m16(8)][k16(2)][lane(32)][8h] @0, Al @4096
//   B block: Bh[n8(16)][lane(32)][8h] @0,       Bl @4096
__device__ __align__(16) __half g_As[(size_t)64 * NCHUNK * 8192];
__device__ __align__(16) __half g_Bs[(size_t)32 * NCHUNK * 8192];
__device__ __align__(16) __half g_Cs[(size_t)32 * NCHUNK * 8192];

__device__ float    g_inva[NSTEP];
__device__ float    g_invb[NMOD];
__device__ float    g_invc[NMOD];
__device__ unsigned g_negmax[NSTEP];
__device__ float    g_perstep[NSTEP];
__device__ float    g_wsum[NSTEP];

__device__ __forceinline__ unsigned fenc(float f) {
    unsigned u = __float_as_uint(f);
    return (u & 0x80000000u) ? ~u : (u | 0x80000000u);
}
__device__ __forceinline__ float fdec(unsigned u) {
    return (u & 0x80000000u) ? __uint_as_float(u & 0x7FFFFFFFu)
                             : __uint_as_float(~u);
}
__device__ __forceinline__ uint32_t smem_u32(const void* p) {
    uint32_t a;
    asm("{ .reg .u64 t; cvta.to.shared.u64 t, %1; cvt.u32.u64 %0, t; }"
        : "=r"(a) : "l"(p));
    return a;
}
__device__ __forceinline__ void cp16(uint32_t dst, const void* src) {
    asm volatile("cp.async.cg.shared.global [%0], [%1], 16;"
                 :: "r"(dst), "l"(src) : "memory");
}
// hi/lo fp16 split of a float2 -> two packed half2 words
__device__ __forceinline__ void splt(float2 v, uint32_t& h, uint32_t& l) {
    __half2 hh = __floats2half2_rn(v.x, v.y);
    float2 hf = __half22float2(hh);
    __half2 ll = __floats2half2_rn(v.x - hf.x, v.y - hf.y);
    h = *reinterpret_cast<uint32_t*>(&hh);
    l = *reinterpret_cast<uint32_t*>(&ll);
}
__device__ __forceinline__ void mma16(float* c, uint4 a, uint32_t b0, uint32_t b1) {
    asm volatile(
        "mma.sync.aligned.m16n8k16.row.col.f32.f16.f16.f32 "
        "{%0,%1,%2,%3}, {%4,%5,%6,%7}, {%8,%9}, {%0,%1,%2,%3};"
        : "+f"(c[0]), "+f"(c[1]), "+f"(c[2]), "+f"(c[3])
        : "r"(a.x), "r"(a.y), "r"(a.z), "r"(a.w), "r"(b0), "r"(b1));
}

// ---------------- init ----------------
__global__ void init_kernel() {
    int i = blockIdx.x * 256 + threadIdx.x;
    if (i < NSTEP) g_negmax[i] = 0u;
}

// ---------------- inverse norms ----------------
template <int WHICH>
__global__ void inv_norm_kernel(const float* __restrict__ X) {
    __shared__ float red[256];
    const int row = blockIdx.x;
    const int tid = threadIdx.x;
    const float4* p = reinterpret_cast<const float4*>(X + (size_t)row * DIM);
    float4 v = p[tid];
    float s = v.x * v.x + v.y * v.y + v.z * v.z + v.w * v.w;
    red[tid] = s;
    __syncthreads();
    for (int off = 128; off > 0; off >>= 1) {
        if (tid < off) red[tid] += red[tid + off];
        __syncthreads();
    }
    if (tid == 0) {
        float inv = 1.0f / fmaxf(sqrtf(red[0]), 1e-8f);
        if (WHICH == 0)      g_inva[row] = inv;
        else if (WHICH == 1) g_invb[row] = inv;
        else                 g_invc[row] = inv;
    }
}

// ---------------- pre-split A into fragment-major fp16 hi/lo ----------------
__global__ void split_a_kernel(const float* __restrict__ src, __half* __restrict__ dst) {
    const int ch = blockIdx.x, rb = blockIdx.y;
    const int tid = threadIdx.x;
    __half* base = dst + ((size_t)rb * NCHUNK + ch) * 8192;
#pragma unroll
    for (int i = 0; i < 2; i++) {
        int s = tid + i * 256;              // 512 slots: [m16(8)][k16(2)][lane(32)]
        int m16 = s >> 6, ki = (s >> 5) & 1, lane = s & 31;
        int g = lane >> 2, t = lane & 3;
        int r0 = rb * 128 + m16 * 16 + g;
        int c0 = ch * KC + ki * 16 + 2 * t;
        float2 v00 = *reinterpret_cast<const float2*>(src + (size_t)r0 * DIM + c0);
        float2 v10 = *reinterpret_cast<const float2*>(src + (size_t)(r0 + 8) * DIM + c0);
        float2 v01 = *reinterpret_cast<const float2*>(src + (size_t)r0 * DIM + c0 + 8);
        float2 v11 = *reinterpret_cast<const float2*>(src + (size_t)(r0 + 8) * DIM + c0 + 8);
        uint4 hi, lo;
        splt(v00, hi.x, lo.x);
        splt(v10, hi.y, lo.y);
        splt(v01, hi.z, lo.z);
        splt(v11, hi.w, lo.w);
        int off16 = (m16 * 2 + ki) * 32 + lane;
        *reinterpret_cast<uint4*>(base + off16 * 8)        = hi;
        *reinterpret_cast<uint4*>(base + 4096 + off16 * 8) = lo;
    }
}

// ---------------- pre-split B/C ----------------
__global__ void split_b_kernel(const float* __restrict__ src, __half* __restrict__ dst) {
    const int ch = blockIdx.x, cb = blockIdx.y;
    const int tid = threadIdx.x;
    __half* base = dst + ((size_t)cb * NCHUNK + ch) * 8192;
#pragma unroll
    for (int i = 0; i < 2; i++) {
        int s = tid + i * 256;              // 512 slots: [n8(16)][lane(32)]
        int n8 = s >> 5, lane = s & 31;
        int g = lane >> 2, t = lane & 3;
        int row = cb * 128 + n8 * 8 + g;
        const float* rp = src + (size_t)row * DIM + ch * KC;
        float2 v0 = *reinterpret_cast<const float2*>(rp + 2 * t);
        float2 v1 = *reinterpret_cast<const float2*>(rp + 2 * t + 8);
        float2 v2 = *reinterpret_cast<const float2*>(rp + 16 + 2 * t);
        float2 v3 = *reinterpret_cast<const float2*>(rp + 16 + 2 * t + 8);
        uint4 hi, lo;
        splt(v0, hi.x, lo.x);
        splt(v1, hi.y, lo.y);
        splt(v2, hi.z, lo.z);
        splt(v3, hi.w, lo.w);
        int off16 = n8 * 32 + lane;
        *reinterpret_cast<uint4*>(base + off16 * 8)        = hi;
        *reinterpret_cast<uint4*>(base + 4096 + off16 * 8) = lo;
    }
}

// ---------------- merged fp16 3-pass GEMM, 512 threads, 4-stage cp.async ----
// blockIdx.x < 32: positive GEMM (store raw dots); >= 32: negative (fused max)
__global__ __launch_bounds__(512, 1)
void gemm_mma(const __half* __restrict__ As, const __half* __restrict__ Bs,
              const __half* __restrict__ Cs, float* __restrict__ Rout) {
    extern __shared__ __half smem[];
    const int tid = threadIdx.x, lane = tid & 31, wid = tid >> 5;
    const int g = lane >> 2, t = lane & 3;
    const int wr = wid >> 2, wc = wid & 3;           // 4x4 warp grid, 32x32 tiles
    const bool store = blockIdx.x < 32;
    const int cb = blockIdx.x & 31;
    const int rowBase = blockIdx.y * 128, colBase = cb * 128;
    const uint32_t sb0 = smem_u32(smem);
    const __half* Ablk = As + (size_t)blockIdx.y * NCHUNK * 8192;
    const __half* Bblk = (store ? Bs : Cs) + (size_t)cb * NCHUNK * 8192;

    float acc[2][4][4];
#pragma unroll
    for (int i = 0; i < 2; i++)
#pragma unroll
        for (int j = 0; j < 4; j++)
#pragma unroll
            for (int q = 0; q < 4; q++) acc[i][j][q] = 0.0f;

    auto issue = [&](int ch, int stg) {
        uint32_t sb = sb0 + stg * STAGE_BYTES;
        const __half* as = Ablk + (size_t)ch * 8192;
        const __half* bs = Bblk + (size_t)ch * 8192;
#pragma unroll
        for (int q = 0; q < 2; q++) {
            int u = tid + q * 512;
            cp16(sb + u * 16, as + u * 8);
        }
#pragma unroll
        for (int q = 0; q < 2; q++) {
            int u = tid + q * 512;
            cp16(sb + 16384 + u * 16, bs + u * 8);
        }
        asm volatile("cp.async.commit_group;" ::: "memory");
    };

    issue(0, 0);
    issue(1, 1);
    issue(2, 2);

    for (int ch = 0; ch < NCHUNK; ch++) {
        if (ch < NCHUNK - 2)
            asm volatile("cp.async.wait_group 2;" ::: "memory");
        else if (ch == NCHUNK - 2)
            asm volatile("cp.async.wait_group 1;" ::: "memory");
        else
            asm volatile("cp.async.wait_group 0;" ::: "memory");
        __syncthreads();
        if (ch + 3 < NCHUNK) issue(ch + 3, (ch + 3) & 3);

        const __half* S  = smem + (ch & 3) * STAGE_H;
        const __half* SB = S + 8192;

#pragma unroll
        for (int ki = 0; ki < 2; ki++) {
            uint4 ah[2], al[2];
#pragma unroll
            for (int mt = 0; mt < 2; mt++) {
                const __half* ap = S + (((wr * 2 + mt) * 2 + ki) * 32 + lane) * 8;
                ah[mt] = *reinterpret_cast<const uint4*>(ap);
                al[mt] = *reinterpret_cast<const uint4*>(ap + 4096);
            }
            uint2 bh[4], bl[4];
#pragma unroll
            for (int nt = 0; nt < 4; nt++) {
                const __half* bp = SB + ((wc * 4 + nt) * 32 + lane) * 8 + ki * 4;
                bh[nt] = *reinterpret_cast<const uint2*>(bp);
                bl[nt] = *reinterpret_cast<const uint2*>(bp + 4096);
            }
#pragma unroll
            for (int mt = 0; mt < 2; mt++)
#pragma unroll
                for (int nt = 0; nt < 4; nt++)
                    mma16(acc[mt][nt], ah[mt], bh[nt].x, bh[nt].y);
#pragma unroll
            for (int mt = 0; mt < 2; mt++)
#pragma unroll
                for (int nt = 0; nt < 4; nt++)
                    mma16(acc[mt][nt], ah[mt], bl[nt].x, bl[nt].y);
#pragma unroll
            for (int mt = 0; mt < 2; mt++)
#pragma unroll
                for (int nt = 0; nt < 4; nt++)
                    mma16(acc[mt][nt], al[mt], bh[nt].x, bh[nt].y);
        }
    }

    // ---------------- epilogue ----------------
    if (store) {
#pragma unroll
        for (int mt = 0; mt < 2; mt++) {
            int r = rowBase + wr * 32 + mt * 16 + g;
#pragma unroll
            for (int nt = 0; nt < 4; nt++) {
                int c = colBase + wc * 32 + nt * 8 + 2 * t;
                *reinterpret_cast<float2*>(Rout + (size_t)r * NMOD + c) =
                    make_float2(acc[mt][nt][0], acc[mt][nt][1]);
                *reinterpret_cast<float2*>(Rout + (size_t)(r + 8) * NMOD + c) =
                    make_float2(acc[mt][nt][2], acc[mt][nt][3]);
            }
        }
    } else {
        float mx0[2], mx1[2];
#pragma unroll
        for (int mt = 0; mt < 2; mt++) { mx0[mt] = -3.402823466e38f; mx1[mt] = -3.402823466e38f; }
#pragma unroll
        for (int nt = 0; nt < 4; nt++) {
            int c = colBase + wc * 32 + nt * 8 + 2 * t;
            float ic0 = g_invc[c], ic1 = g_invc[c + 1];
#pragma unroll
            for (int mt = 0; mt < 2; mt++) {
                mx0[mt] = fmaxf(mx0[mt], fmaxf(acc[mt][nt][0] * ic0, acc[mt][nt][1] * ic1));
                mx1[mt] = fmaxf(mx1[mt], fmaxf(acc[mt][nt][2] * ic0, acc[mt][nt][3] * ic1));
            }
        }
#pragma unroll
        for (int mt = 0; mt < 2; mt++) {
            mx0[mt] = fmaxf(mx0[mt], __shfl_xor_sync(0xFFFFFFFF, mx0[mt], 1));
            mx0[mt] = fmaxf(mx0[mt], __shfl_xor_sync(0xFFFFFFFF, mx0[mt], 2));
            mx1[mt] = fmaxf(mx1[mt], __shfl_xor_sync(0xFFFFFFFF, mx1[mt], 1));
            mx1[mt] = fmaxf(mx1[mt], __shfl_xor_sync(0xFFFFFFFF, mx1[mt], 2));
        }
        if (t == 0) {
#pragma unroll
            for (int mt = 0; mt < 2; mt++) {
                int r = rowBase + wr * 32 + mt * 16 + g;
                atomicMax(&g_negmax[r], fenc(mx0[mt]));
                atomicMax(&g_negmax[r + 8], fenc(mx1[mt]));
            }
        }
    }
}

// ---------------- per-row stats + softmax rewrite in place ----------------
__global__ void row_stats_kernel(float* __restrict__ attn,
                                 float* __restrict__ perstep_out) {
    __shared__ float red[256];
    __shared__ float bc[4];
    const int row = blockIdx.x;
    const int tid = threadIdx.x;
    float* Rrow = attn + (size_t)row * NMOD;

    float v[16], ib[16];
#pragma unroll
    for (int q = 0; q < 16; q++) {
        int j = tid + q * 256;
        v[q]  = Rrow[j];
        ib[q] = g_invb[j];
    }

    float mr = -3.402823466e38f, mrb = -3.402823466e38f;
#pragma unroll
    for (int q = 0; q < 16; q++) {
        mr  = fmaxf(mr, v[q]);
        mrb = fmaxf(mrb, v[q] * ib[q]);
    }

    red[tid] = mr; __syncthreads();
    for (int off = 128; off > 0; off >>= 1) {
        if (tid < off) red[tid] = fmaxf(red[tid], red[tid + off]);
        __syncthreads();
    }
    if (tid == 0) bc[0] = red[0];
    __syncthreads();

    red[tid] = mrb; __syncthreads();
    for (int off = 128; off > 0; off >>= 1) {
        if (tid < off) red[tid] = fmaxf(red[tid], red[tid + off]);
        __syncthreads();
    }
    if (tid == 0) bc[1] = red[0];
    __syncthreads();

    const float maxR = bc[0];
    float e[16];
    float dsum = 0.0f, ws = 0.0f;
#pragma unroll
    for (int q = 0; q < 16; q++) {
        float ev = __expf((v[q] - maxR) * INVT);
        e[q] = ev;
        dsum += ev;
        ws   += v[q] * ib[q] * ev;
    }

    red[tid] = dsum; __syncthreads();
    for (int off = 128; off > 0; off >>= 1) {
        if (tid < off) red[tid] += red[tid + off];
        __syncthreads();
    }
    if (tid == 0) bc[2] = red[0];
    __syncthreads();

    red[tid] = ws; __syncthreads();
    for (int off = 128; off > 0; off >>= 1) {
        if (tid < off) red[tid] += red[tid + off];
        __syncthreads();
    }
    if (tid == 0) bc[3] = red[0];
    __syncthreads();

    const float invd = 1.0f / bc[2];
#pragma unroll
    for (int q = 0; q < 16; q++)
        Rrow[tid + q * 256] = e[q] * invd;

    if (tid == 0) {
        float inva = g_inva[row];
        float ps = bc[1] * inva;
        g_perstep[row]  = ps;
        perstep_out[row] = ps;
        g_wsum[row] = inva * bc[3] * invd;
    }
}

// ---------------- final scalar reductions ----------------
__global__ void finalize_kernel(float* __restrict__ out) {
    __shared__ float r0[1024], r1[1024], r2[1024], r3[1024];
    const int tid = threadIdx.x;
    float s = 0.0f, mn = 3.402823466e38f, ws = 0.0f, ng = 0.0f;
#pragma unroll
    for (int q = 0; q < 8; q++) {
        int i = tid + q * 1024;
        float ps = g_perstep[i];
        s += ps;
        mn = fminf(mn, ps);
        ws += g_wsum[i];
        ng += fdec(g_negmax[i]) * g_inva[i];
    }
    r0[tid] = s; r1[tid] = mn; r2[tid] = ws; r3[tid] = ng;
    __syncthreads();
    for (int off = 512; off > 0; off >>= 1) {
        if (tid < off) {
            r0[tid] += r0[tid + off];
            r1[tid] = fminf(r1[tid], r1[tid + off]);
            r2[tid] += r2[tid + off];
            r3[tid] += r3[tid + off];
        }
        __syncthreads();
    }
    if (tid == 0) {
        float alignment = r0[0] * (1.0f / NSTEP);
        float weighted  = r2[0] * (1.0f / NSTEP);
        float neg       = r3[0] * (1.0f / NSTEP);
        float contrast  = alignment - neg;
        float margin    = fmaxf(contrast - 0.2f, 0.0f);
        float overall   = 0.7f * weighted + 0.3f * contrast;
        out[0] = alignment;
        out[1] = weighted;
        float* tl = out + 2 + (size_t)NSTEP * NMOD;
        tl[0] = contrast;
        tl[1] = margin;
        tl[2] = alignment;
        tl[3] = neg;
        tl[4 + NSTEP] = r1[0];
        tl[5 + NSTEP] = overall;
    }
}

// ---------------- launch ----------------
extern "C" void kernel_launch(void* const* d_in, const int* in_sizes, int n_in,
                              void* d_out, int out_size) {
    (void)in_sizes; (void)n_in; (void)out_size;
    const float* A = (const float*)d_in[0];
    const float* B = (const float*)d_in[1];
    const float* C = (const float*)d_in[2];
    float* out  = (float*)d_out;
    float* attn = out + 2;
    float* perstep = out + 2 + (size_t)NSTEP * NMOD + 4;

    __half* As_p; cudaGetSymbolAddress((void**)&As_p, g_As);
    __half* Bs_p; cudaGetSymbolAddress((void**)&Bs_p, g_Bs);
    __half* Cs_p; cudaGetSymbolAddress((void**)&Cs_p, g_Cs);

    cudaFuncSetAttribute(gemm_mma, cudaFuncAttributeMaxDynamicSharedMemorySize, SMEM_BYTES);

    init_kernel<<<(NSTEP + 255) / 256, 256>>>();
    inv_norm_kernel<0><<<NSTEP, 256>>>(A);
    inv_norm_kernel<1><<<NMOD, 256>>>(B);
    inv_norm_kernel<2><<<NMOD, 256>>>(C);

    split_a_kernel<<<dim3(NCHUNK, 64), 256>>>(A, As_p);
    split_b_kernel<<<dim3(NCHUNK, 32), 256>>>(B, Bs_p);
    split_b_kernel<<<dim3(NCHUNK, 32), 256>>>(C, Cs_p);

    gemm_mma<<<dim3(64, 64), 512, SMEM_BYTES>>>(As_p, Bs_p, Cs_p, attn);

    row_stats_kernel<<<NSTEP, 256>>>(attn, perstep);
    finalize_kernel<<<1, 1024>>>(out);
}